// round 3
// baseline (speedup 1.0000x reference)
#include <cuda_runtime.h>
#include <cuda_bf16.h>

#define SEQ   512
#define BATCH 256
#define HID   128
#define MROWS (SEQ * BATCH)        /* 131072 */
#define KIN   300
#define KINP  304                  /* padded */
#define ALPHA 0.1f

typedef unsigned long long u64;

__device__ __forceinline__ u64 pack2(float lo, float hi) {
    u64 r;
    asm("mov.b64 %0, {%1, %2};" : "=l"(r) : "f"(lo), "f"(hi));
    return r;
}
__device__ __forceinline__ float2 unpack2(u64 v) {
    float2 f;
    asm("mov.b64 {%0, %1}, %2;" : "=f"(f.x), "=f"(f.y) : "l"(v));
    return f;
}
__device__ __forceinline__ void fma2(u64 &acc, u64 a, u64 b) {
    asm("fma.rn.f32x2 %0, %1, %2, %0;" : "+l"(acc) : "l"(a), "l"(b));
}

/* scratch */
__device__ float g_xp[MROWS * HID];
__device__ float g_hs[MROWS * HID];
__device__ float g_WTih[KINP * HID];
__device__ float g_WT1[HID * 64];
__device__ float g_bias[HID];

/* ------------------------------------------------------------------ */
__global__ void prep_kernel(const float* __restrict__ W_ih,
                            const float* __restrict__ W1,
                            const float* __restrict__ b_ih,
                            const float* __restrict__ b_hh)
{
    const int i = blockIdx.x * 256 + threadIdx.x;
    if (i < KINP * HID) {
        const int k = i >> 7, n = i & 127;
        g_WTih[i] = (k < KIN) ? W_ih[n * KIN + k] : 0.f;
    }
    if (i < HID * 64) {
        const int k = i >> 6, n = i & 63;
        g_WT1[i] = W1[n * HID + k];
    }
    if (i < HID) g_bias[i] = b_ih[i] + b_hh[i];
}

/* ------------------------------------------------------------------ */
/* proj: xp[M][128] = x[M][300] @ WT[304][128]; BK=8, double-buffered */
/* ------------------------------------------------------------------ */
__global__ __launch_bounds__(256)
void proj_kernel(const float* __restrict__ A, const float* __restrict__ WT,
                 const float* __restrict__ bias, float* __restrict__ C)
{
    constexpr int BN = 128, BK = 8, AST = 132, NT = KINP / BK;
    __shared__ __align__(16) float As[2][BK * AST];
    __shared__ __align__(16) float Bs[2][BK * BN];

    const int tid = threadIdx.x;
    const int tx  = tid & 15;
    const int ty  = tid >> 4;
    const int blockM = blockIdx.x * 128;

    u64 acc[8][4];
#pragma unroll
    for (int i = 0; i < 8; i++)
#pragma unroll
        for (int j = 0; j < 4; j++) acc[i][j] = 0ull;

    /* load mappings: one float4 of A and one of B per thread per tile */
    const int ar_  = tid >> 1;            /* A row 0..127  */
    const int ak4  = (tid & 1) * 4;       /* A k offset    */
    const int bk   = tid >> 5;            /* B k row 0..7  */
    const int bn4  = (tid & 31) * 4;      /* B n offset    */
    const float* Arow = A + (long)(blockM + ar_) * KIN;

    /* prologue: tile 0 */
    {
        float4 av = make_float4(0.f, 0.f, 0.f, 0.f);
        if (ak4 < KIN) av = *(const float4*)(Arow + ak4);
        As[0][(ak4 + 0) * AST + ar_] = av.x;
        As[0][(ak4 + 1) * AST + ar_] = av.y;
        As[0][(ak4 + 2) * AST + ar_] = av.z;
        As[0][(ak4 + 3) * AST + ar_] = av.w;
        *(float4*)&Bs[0][bk * BN + bn4] = *(const float4*)(WT + bk * BN + bn4);
    }
    __syncthreads();

    for (int kt = 0; kt < NT; ++kt) {
        const int cur = kt & 1;
        float4 av, bv;
        const bool more = (kt + 1 < NT);
        if (more) {
            const int k0 = (kt + 1) * BK;
            av = make_float4(0.f, 0.f, 0.f, 0.f);
            if (k0 + ak4 < KIN) av = *(const float4*)(Arow + k0 + ak4);
            bv = *(const float4*)(WT + (k0 + bk) * BN + bn4);
        }

#pragma unroll
        for (int kk = 0; kk < BK; ++kk) {
            const float4 a0 = *(const float4*)&As[cur][kk * AST + ty * 8];
            const float4 a1 = *(const float4*)&As[cur][kk * AST + ty * 8 + 4];
            const ulonglong2 b0 = *(const ulonglong2*)&Bs[cur][kk * BN + tx * 8];
            const ulonglong2 b1 = *(const ulonglong2*)&Bs[cur][kk * BN + tx * 8 + 4];
            const u64 bp[4] = { b0.x, b0.y, b1.x, b1.y };
            const float ar[8] = {a0.x, a0.y, a0.z, a0.w, a1.x, a1.y, a1.z, a1.w};
#pragma unroll
            for (int i = 0; i < 8; i++) {
                const u64 ai = pack2(ar[i], ar[i]);
#pragma unroll
                for (int j = 0; j < 4; j++) fma2(acc[i][j], ai, bp[j]);
            }
        }

        if (more) {
            const int nxt = cur ^ 1;
            As[nxt][(ak4 + 0) * AST + ar_] = av.x;
            As[nxt][(ak4 + 1) * AST + ar_] = av.y;
            As[nxt][(ak4 + 2) * AST + ar_] = av.z;
            As[nxt][(ak4 + 3) * AST + ar_] = av.w;
            *(float4*)&Bs[nxt][bk * BN + bn4] = bv;
        }
        __syncthreads();
    }

#pragma unroll
    for (int i = 0; i < 8; i++) {
        float* Crow = C + (long)(blockM + ty * 8 + i) * BN;
#pragma unroll
        for (int j = 0; j < 4; j++) {
            const float2 v = unpack2(acc[i][j]);
            const int n = tx * 8 + 2 * j;
            *(float2*)(Crow + n) = make_float2(v.x + bias[n], v.y + bias[n + 1]);
        }
    }
}

/* ------------------------------------------------------------------ */
/* scan (unchanged): FMA-bound at 256 cyc/step                        */
/* ------------------------------------------------------------------ */
__global__ __launch_bounds__(512)
void scan_kernel(const float* __restrict__ xp, const float* __restrict__ Whh,
                 float* __restrict__ hs)
{
    const int tid = threadIdx.x;
    const int j   = tid >> 2;
    const int seg = tid & 3;
    const int b0  = blockIdx.x * 2;

    __shared__ __align__(16) float hbuf[2][2][144];

    u64 w[16];
    const u64* wp = (const u64*)(Whh + j * HID + seg * 32);
#pragma unroll
    for (int i = 0; i < 16; i++) w[i] = wp[i];

    for (int i = tid; i < 2 * 144; i += 512) ((float*)hbuf[0])[i] = 0.f;

    const bool writer = (seg < 2);
    const int  wb     = seg;
    float xcur = 0.f;
    if (writer) xcur = xp[((long)0 * BATCH + b0 + wb) * HID + j];
    __syncthreads();

    int pp = 0;
    for (int t = 0; t < SEQ; ++t) {
        float xnext = 0.f;
        if (writer && t + 1 < SEQ)
            xnext = xp[((long)(t + 1) * BATCH + b0 + wb) * HID + j];

        u64 acc0 = 0ull, acc1 = 0ull;
        const ulonglong2* h0p = (const ulonglong2*)&hbuf[pp][0][seg * 36];
        const ulonglong2* h1p = (const ulonglong2*)&hbuf[pp][1][seg * 36];
#pragma unroll
        for (int i = 0; i < 8; i++) {
            const ulonglong2 h0v = h0p[i];
            fma2(acc0, w[2 * i + 0], h0v.x);
            fma2(acc0, w[2 * i + 1], h0v.y);
            const ulonglong2 h1v = h1p[i];
            fma2(acc1, w[2 * i + 0], h1v.x);
            fma2(acc1, w[2 * i + 1], h1v.y);
        }
        const float2 a0 = unpack2(acc0);
        const float2 a1 = unpack2(acc1);
        float s0 = a0.x + a0.y;
        float s1 = a1.x + a1.y;
        s0 += __shfl_xor_sync(0xffffffffu, s0, 1);
        s0 += __shfl_xor_sync(0xffffffffu, s0, 2);
        s1 += __shfl_xor_sync(0xffffffffu, s1, 1);
        s1 += __shfl_xor_sync(0xffffffffu, s1, 2);

        if (writer) {
            const float v = xcur + (wb == 0 ? s0 : s1);
            const float e = __expf(v + v);
            const float h = 1.f - __fdividef(2.f, e + 1.f);
            hbuf[pp ^ 1][wb][j + (j >> 5) * 4] = h;
            hs[((long)t * BATCH + b0 + wb) * HID + j] = h;
        }
        xcur = xnext;
        pp ^= 1;
        __syncthreads();
    }
}

/* ------------------------------------------------------------------ */
/* Fused MLP: L1 GEMM (double-buffered) -> smem y1 -> k-split tail.   */
/* 256 threads; tail: 2 threads per row, shfl-reduce per output.      */
/* ------------------------------------------------------------------ */
__global__ __launch_bounds__(256)
void mlp_kernel(const float* __restrict__ A, const float* __restrict__ WT1,
                const float* __restrict__ b1,
                const float* __restrict__ W2, const float* __restrict__ b2,
                const float* __restrict__ W3, const float* __restrict__ b3,
                const float* __restrict__ W4, const float* __restrict__ b4,
                const float* __restrict__ W5, const float* __restrict__ b5,
                float* __restrict__ out)
{
    constexpr int BN = 64, BK = 8, AST = 132, YST = 66, NT = HID / BK;
    __shared__ __align__(16) float As[2][BK * AST];   /* reused: sW2 (2048) */
    __shared__ __align__(16) float Bs[2][BK * BN];    /* reused: tail wts   */
    __shared__ __align__(16) float y1s[128 * YST];

    const int tid = threadIdx.x;
    const int tx  = tid & 15;
    const int ty  = tid >> 4;
    const int blockM = blockIdx.x * 128;

    u64 acc[8][2];
#pragma unroll
    for (int i = 0; i < 8; i++) { acc[i][0] = 0ull; acc[i][1] = 0ull; }

    const int ar_ = tid >> 1;
    const int ak4 = (tid & 1) * 4;
    const int bk  = tid >> 5;             /* 0..7 */
    const int bn2 = (tid & 31) * 2;       /* 0..62 */
    const float* Arow = A + (long)(blockM + ar_) * HID;

    {
        const float4 av = *(const float4*)(Arow + ak4);
        As[0][(ak4 + 0) * AST + ar_] = av.x;
        As[0][(ak4 + 1) * AST + ar_] = av.y;
        As[0][(ak4 + 2) * AST + ar_] = av.z;
        As[0][(ak4 + 3) * AST + ar_] = av.w;
        *(float2*)&Bs[0][bk * BN + bn2] = *(const float2*)(WT1 + bk * BN + bn2);
    }
    __syncthreads();

    for (int kt = 0; kt < NT; ++kt) {
        const int cur = kt & 1;
        float4 av; float2 bv;
        const bool more = (kt + 1 < NT);
        if (more) {
            const int k0 = (kt + 1) * BK;
            av = *(const float4*)(Arow + k0 + ak4);
            bv = *(const float2*)(WT1 + (k0 + bk) * BN + bn2);
        }

#pragma unroll
        for (int kk = 0; kk < BK; ++kk) {
            const float4 a0 = *(const float4*)&As[cur][kk * AST + ty * 8];
            const float4 a1 = *(const float4*)&As[cur][kk * AST + ty * 8 + 4];
            const ulonglong2 b0 = *(const ulonglong2*)&Bs[cur][kk * BN + tx * 4];
            const float ar[8] = {a0.x, a0.y, a0.z, a0.w, a1.x, a1.y, a1.z, a1.w};
#pragma unroll
            for (int i = 0; i < 8; i++) {
                const u64 ai = pack2(ar[i], ar[i]);
                fma2(acc[i][0], ai, b0.x);
                fma2(acc[i][1], ai, b0.y);
            }
        }

        if (more) {
            const int nxt = cur ^ 1;
            As[nxt][(ak4 + 0) * AST + ar_] = av.x;
            As[nxt][(ak4 + 1) * AST + ar_] = av.y;
            As[nxt][(ak4 + 2) * AST + ar_] = av.z;
            As[nxt][(ak4 + 3) * AST + ar_] = av.w;
            *(float2*)&Bs[nxt][bk * BN + bn2] = bv;
        }
        __syncthreads();
    }

    /* L1 epilogue -> smem */
#pragma unroll
    for (int i = 0; i < 8; i++) {
        const int m = ty * 8 + i;
#pragma unroll
        for (int j = 0; j < 2; j++) {
            const float2 v = unpack2(acc[i][j]);
            const int n = tx * 4 + 2 * j;
            float v0 = v.x + b1[n];
            float v1 = v.y + b1[n + 1];
            v0 = v0 > 0.f ? v0 : ALPHA * v0;
            v1 = v1 > 0.f ? v1 : ALPHA * v1;
            *(float2*)&y1s[m * YST + n] = make_float2(v0, v1);
        }
    }

    /* tail weights into reused smem */
    float* const sW2 = (float*)As;              /* 2048 */
    float* const sW3 = (float*)Bs;              /* 512  */
    float* const sW4 = (float*)Bs + 512;        /* 128  */
    float* const sW5 = (float*)Bs + 640;        /* 8    */
    float* const sb2 = (float*)Bs + 648;        /* 32   */
    float* const sb3 = (float*)Bs + 680;        /* 16   */
    float* const sb4 = (float*)Bs + 696;        /* 8    */
    float* const sb5 = (float*)Bs + 704;        /* 1    */

    for (int i = tid; i < 2048; i += 256) sW2[i] = W2[i];
    for (int i = tid; i < 512;  i += 256) sW3[i] = W3[i];
    if (tid < 128) sW4[tid] = W4[tid];
    if (tid < 32)  sb2[tid] = b2[tid];
    if (tid < 16)  sb3[tid] = b3[tid];
    if (tid < 8) { sb4[tid] = b4[tid]; sW5[tid] = W5[tid]; }
    if (tid == 0)  sb5[0] = b5[0];
    __syncthreads();

    /* tail: 2 threads per row (k-split), shfl.xor(1) reductions */
    const int row  = tid >> 1;
    const int half = tid & 1;

    u64 ap[16];
    const u64* yr = (const u64*)&y1s[row * YST + half * 32];
#pragma unroll
    for (int i = 0; i < 16; i++) ap[i] = yr[i];

    const u64* w2p = (const u64*)sW2;
    const u64* w3p = (const u64*)sW3;
    const u64* w4p = (const u64*)sW4;
    const u64* w5p = (const u64*)sW5;

    /* L2: 64 -> 32 */
    float y2[32];
#pragma unroll
    for (int o = 0; o < 32; o++) {
        u64 a = 0ull;
        const ulonglong2* wv = (const ulonglong2*)&w2p[o * 32 + half * 16];
#pragma unroll
        for (int k = 0; k < 8; k++) {
            const ulonglong2 wk = wv[k];
            fma2(a, ap[2 * k],     wk.x);
            fma2(a, ap[2 * k + 1], wk.y);
        }
        const float2 f = unpack2(a);
        float s = f.x + f.y;
        s += __shfl_xor_sync(0xffffffffu, s, 1);
        s += sb2[o];
        y2[o] = s > 0.f ? s : ALPHA * s;
    }

    /* L3: 32 -> 16 */
    u64 a2[8];
#pragma unroll
    for (int i = 0; i < 8; i++) a2[i] = pack2(y2[half * 16 + 2 * i], y2[half * 16 + 2 * i + 1]);
    float y3[16];
#pragma unroll
    for (int o = 0; o < 16; o++) {
        u64 a = 0ull;
        const ulonglong2* wv = (const ulonglong2*)&w3p[o * 16 + half * 8];
#pragma unroll
        for (int k = 0; k < 4; k++) {
            const ulonglong2 wk = wv[k];
            fma2(a, a2[2 * k],     wk.x);
            fma2(a, a2[2 * k + 1], wk.y);
        }
        const float2 f = unpack2(a);
        float s = f.x + f.y;
        s += __shfl_xor_sync(0xffffffffu, s, 1);
        s += sb3[o];
        y3[o] = s > 0.f ? s : ALPHA * s;
    }

    /* L4: 16 -> 8 */
    u64 a3[4];
#pragma unroll
    for (int i = 0; i < 4; i++) a3[i] = pack2(y3[half * 8 + 2 * i], y3[half * 8 + 2 * i + 1]);
    float y4[8];
#pragma unroll
    for (int o = 0; o < 8; o++) {
        u64 a = 0ull;
        const ulonglong2* wv = (const ulonglong2*)&w4p[o * 8 + half * 4];
#pragma unroll
        for (int k = 0; k < 2; k++) {
            const ulonglong2 wk = wv[k];
            fma2(a, a3[2 * k],     wk.x);
            fma2(a, a3[2 * k + 1], wk.y);
        }
        const float2 f = unpack2(a);
        float s = f.x + f.y;
        s += __shfl_xor_sync(0xffffffffu, s, 1);
        s += sb4[o];
        y4[o] = s > 0.f ? s : ALPHA * s;
    }

    /* L5: 8 -> 1 */
    u64 a4[2];
#pragma unroll
    for (int i = 0; i < 2; i++) a4[i] = pack2(y4[half * 4 + 2 * i], y4[half * 4 + 2 * i + 1]);
    {
        u64 a = 0ull;
        const ulonglong2 wk = *(const ulonglong2*)&w5p[half * 2];
        fma2(a, a4[0], wk.x);
        fma2(a, a4[1], wk.y);
        const float2 f = unpack2(a);
        float s = f.x + f.y;
        s += __shfl_xor_sync(0xffffffffu, s, 1);
        s += sb5[0];
        s = s > 0.f ? s : ALPHA * s;
        if (half == 0) out[blockM + row] = s;
    }
}

/* ------------------------------------------------------------------ */
extern "C" void kernel_launch(void* const* d_in, const int* in_sizes, int n_in,
                              void* d_out, int out_size)
{
    const float* x    = (const float*)d_in[0];
    const float* W_ih = (const float*)d_in[1];
    const float* W_hh = (const float*)d_in[2];
    const float* b_ih = (const float*)d_in[3];
    const float* b_hh = (const float*)d_in[4];
    const float* W1   = (const float*)d_in[5];
    const float* b1   = (const float*)d_in[6];
    const float* W2   = (const float*)d_in[7];
    const float* b2   = (const float*)d_in[8];
    const float* W3   = (const float*)d_in[9];
    const float* b3   = (const float*)d_in[10];
    const float* W4   = (const float*)d_in[11];
    const float* b4   = (const float*)d_in[12];
    const float* W5   = (const float*)d_in[13];
    const float* b5   = (const float*)d_in[14];
    float* out = (float*)d_out;

    float *xp, *hs, *WTih, *WT1;
    cudaGetSymbolAddress((void**)&xp,   g_xp);
    cudaGetSymbolAddress((void**)&hs,   g_hs);
    cudaGetSymbolAddress((void**)&WTih, g_WTih);
    cudaGetSymbolAddress((void**)&WT1,  g_WT1);
    float* bias;
    cudaGetSymbolAddress((void**)&bias, g_bias);

    prep_kernel<<<(KINP * HID + 255) / 256, 256>>>(W_ih, W1, b_ih, b_hh);
    proj_kernel<<<MROWS / 128, 256>>>(x, WTih, bias, xp);
    scan_kernel<<<BATCH / 2, 512>>>(xp, W_hh, hs);
    mlp_kernel<<<MROWS / 128, 256>>>(hs, WT1, b1, W2, b2, W3, b3, W4, b4, W5, b5, out);
}

// round 6
// speedup vs baseline: 1.2204x; 1.2204x over previous
#include <cuda_runtime.h>
#include <cuda_bf16.h>
#include <cstdint>

#define SEQ   512
#define BATCH 256
#define HID   128
#define MROWS (SEQ * BATCH)        /* 131072 */
#define KIN   300
#define KPAD  320                  /* 5 chunks of 64 */
#define ALPHA 0.1f

typedef unsigned long long u64;

/* ---------------- packed f32x2 helpers ----------------------------- */
__device__ __forceinline__ u64 pack2(float lo, float hi) {
    u64 r; asm("mov.b64 %0, {%1, %2};" : "=l"(r) : "f"(lo), "f"(hi)); return r;
}
__device__ __forceinline__ float2 unpack2(u64 v) {
    float2 f; asm("mov.b64 {%0, %1}, %2;" : "=f"(f.x), "=f"(f.y) : "l"(v)); return f;
}
__device__ __forceinline__ void fma2(u64 &acc, u64 a, u64 b) {
    asm("fma.rn.f32x2 %0, %1, %2, %0;" : "+l"(acc) : "l"(a), "l"(b));
}

/* ---------------- warp-MMA helpers (sm_80+ baseline PTX) ----------- */
__device__ __forceinline__ uint32_t smem_u32(const void* p) {
    uint32_t a;
    asm("{ .reg .u64 t; cvta.to.shared.u64 t, %1; cvt.u32.u64 %0, t; }" : "=r"(a) : "l"(p));
    return a;
}
#define SW128(off) ((off) ^ (((off) >> 3) & 0x70))

__device__ __forceinline__ void ldsm4(uint32_t &r0, uint32_t &r1, uint32_t &r2, uint32_t &r3,
                                      uint32_t addr) {
    asm volatile("ldmatrix.sync.aligned.m8n8.x4.shared.b16 {%0,%1,%2,%3}, [%4];"
                 : "=r"(r0), "=r"(r1), "=r"(r2), "=r"(r3) : "r"(addr));
}
__device__ __forceinline__ void mma16816(float* d, const uint32_t* a, const uint32_t* b) {
    asm volatile("mma.sync.aligned.m16n8k16.row.col.f32.bf16.bf16.f32 "
                 "{%0,%1,%2,%3}, {%4,%5,%6,%7}, {%8,%9}, {%0,%1,%2,%3};"
                 : "+f"(d[0]), "+f"(d[1]), "+f"(d[2]), "+f"(d[3])
                 : "r"(a[0]), "r"(a[1]), "r"(a[2]), "r"(a[3]), "r"(b[0]), "r"(b[1]));
}

/* split one float4 into packed bf16x2 hi / lo words */
__device__ __forceinline__ void split4(float4 v, uint32_t &hp0, uint32_t &hp1,
                                       uint32_t &lp0, uint32_t &lp1) {
    const __nv_bfloat16 h0 = __float2bfloat16_rn(v.x);
    const __nv_bfloat16 h1 = __float2bfloat16_rn(v.y);
    const __nv_bfloat16 h2 = __float2bfloat16_rn(v.z);
    const __nv_bfloat16 h3 = __float2bfloat16_rn(v.w);
    __nv_bfloat162 t0 = __halves2bfloat162(h0, h1);
    __nv_bfloat162 t1 = __halves2bfloat162(h2, h3);
    hp0 = *(uint32_t*)&t0; hp1 = *(uint32_t*)&t1;
    __nv_bfloat162 u0 = __halves2bfloat162(__float2bfloat16_rn(v.x - __bfloat162float(h0)),
                                           __float2bfloat16_rn(v.y - __bfloat162float(h1)));
    __nv_bfloat162 u1 = __halves2bfloat162(__float2bfloat16_rn(v.z - __bfloat162float(h2)),
                                           __float2bfloat16_rn(v.w - __bfloat162float(h3)));
    lp0 = *(uint32_t*)&u0; lp1 = *(uint32_t*)&u1;
}

#define STS128(addr, a, b, c_, d_) \
    asm volatile("st.shared.v4.b32 [%0], {%1,%2,%3,%4};" :: "r"(addr), \
                 "r"(a), "r"(b), "r"(c_), "r"(d_) : "memory")

/* ---------------- scratch ------------------------------------------ */
__device__ float g_xp[MROWS * HID];
__device__ float g_hs[MROWS * HID];
__device__ __nv_bfloat16 g_Wbh[HID * KPAD];   /* W_ih hi  [n][k] */
__device__ __nv_bfloat16 g_Wbl[HID * KPAD];   /* W_ih lo  [n][k] */
__device__ __nv_bfloat16 g_W1h[64 * HID];     /* W1 hi    [n][k] */
__device__ __nv_bfloat16 g_W1l[64 * HID];     /* W1 lo    [n][k] */
__device__ float g_bias[HID];

/* ------------------------------------------------------------------ */
__global__ void prep_kernel(const float* __restrict__ W_ih,
                            const float* __restrict__ W1,
                            const float* __restrict__ b_ih,
                            const float* __restrict__ b_hh)
{
    const int i = blockIdx.x * 256 + threadIdx.x;
    if (i < HID * KPAD) {
        const int n = i / KPAD, k = i % KPAD;
        const float w = (k < KIN) ? W_ih[n * KIN + k] : 0.f;
        const __nv_bfloat16 h = __float2bfloat16_rn(w);
        g_Wbh[i] = h;
        g_Wbl[i] = __float2bfloat16_rn(w - __bfloat162float(h));
    }
    if (i < 64 * HID) {
        const float w = W1[i];
        const __nv_bfloat16 h = __float2bfloat16_rn(w);
        g_W1h[i] = h;
        g_W1l[i] = __float2bfloat16_rn(w - __bfloat162float(h));
    }
    if (i < HID) g_bias[i] = b_ih[i] + b_hh[i];
}

/* ------------------------------------------------------------------ */
/* proj: xp[M][128] = x[M][300] @ W_ih^T via warp-MMA bf16 3-product  */
/* CTA: 128x128, K in 5 chunks of 64; warps 4(m) x 2(n), tile 32x64.  */
/* ------------------------------------------------------------------ */
#define PROJ_SMEM (4 * 16384)

__global__ __launch_bounds__(256)
void proj_mma_kernel(const float* __restrict__ x,
                     const __nv_bfloat16* __restrict__ Wbh,
                     const __nv_bfloat16* __restrict__ Wbl,
                     const float* __restrict__ bias, float* __restrict__ C)
{
    extern __shared__ __align__(1024) char sm[];
    const uint32_t base = smem_u32(sm);
    const uint32_t A_H = base, A_L = base + 16384;
    const uint32_t B_H = base + 32768, B_L = base + 49152;

    const int tid  = threadIdx.x;
    const int lane = tid & 31;
    const int wid  = tid >> 5;
    const int wm   = wid & 3;          /* m tile 0..3 (32 rows) */
    const int wn   = wid >> 2;         /* n tile 0..1 (64 cols) */
    const int blockM = blockIdx.x * 128;

    float d[2][8][4];
#pragma unroll
    for (int mi = 0; mi < 2; mi++)
#pragma unroll
        for (int ni = 0; ni < 8; ni++)
#pragma unroll
            for (int q = 0; q < 4; q++) d[mi][ni][q] = 0.f;

    /* staging mapping: 2 threads per row, each does 32 k */
    const int srow  = tid >> 1;
    const int shalf = (tid & 1) * 32;
    const float* xrow = x + (long)(blockM + srow) * KIN;
    const uint32_t arow = srow * 128 + shalf * 2;

    /* ldmatrix lane->address components */
    const int rowA = (lane & 7) + ((lane >> 3) & 1) * 8;
    const int kxA  = (lane >> 4) * 16;                    /* bytes */
    const int rowB = (lane & 7) + (lane >> 4) * 8;
    const int kxB  = ((lane >> 3) & 1) * 16;

    for (int c = 0; c < 5; ++c) {
        /* ---- stage A (fp32 -> bf16 hi/lo, swizzled) ---- */
#pragma unroll
        for (int i = 0; i < 8; i += 2) {
            uint32_t h0, h1, h2, h3, l0, l1, l2, l3;
            {
                const int gcol = c * 64 + shalf + i * 4;
                float4 v = make_float4(0.f, 0.f, 0.f, 0.f);
                if (gcol < KIN) v = *(const float4*)(xrow + gcol);
                split4(v, h0, h1, l0, l1);
            }
            {
                const int gcol = c * 64 + shalf + (i + 1) * 4;
                float4 v = make_float4(0.f, 0.f, 0.f, 0.f);
                if (gcol < KIN) v = *(const float4*)(xrow + gcol);
                split4(v, h2, h3, l2, l3);
            }
            const uint32_t off = SW128(arow + i * 8);
            STS128(A_H + off, h0, h1, h2, h3);
            STS128(A_L + off, l0, l1, l2, l3);
        }
        /* ---- stage B (prepacked bf16, swizzled) ---- */
        {
            const __nv_bfloat16* bhp = Wbh + srow * KPAD + c * 64 + shalf;
            const __nv_bfloat16* blp = Wbl + srow * KPAD + c * 64 + shalf;
#pragma unroll
            for (int i = 0; i < 4; i++) {
                const uint4 hv = *(const uint4*)(bhp + i * 8);
                const uint4 lv = *(const uint4*)(blp + i * 8);
                const uint32_t off = SW128(arow + i * 16);
                STS128(B_H + off, hv.x, hv.y, hv.z, hv.w);
                STS128(B_L + off, lv.x, lv.y, lv.z, lv.w);
            }
        }
        __syncthreads();

        /* ---- compute: 4 k16 steps ---- */
#pragma unroll
        for (int ks = 0; ks < 4; ++ks) {
            uint32_t ah[2][4], al[2][4];
#pragma unroll
            for (int mi = 0; mi < 2; mi++) {
                const uint32_t off = SW128((uint32_t)((wm * 32 + mi * 16 + rowA) * 128
                                                      + ks * 32 + kxA));
                ldsm4(ah[mi][0], ah[mi][1], ah[mi][2], ah[mi][3], A_H + off);
                ldsm4(al[mi][0], al[mi][1], al[mi][2], al[mi][3], A_L + off);
            }
            uint32_t bh[8][2], bl[8][2];
#pragma unroll
            for (int nb = 0; nb < 4; nb++) {
                const uint32_t off = SW128((uint32_t)((wn * 64 + nb * 16 + rowB) * 128
                                                      + ks * 32 + kxB));
                uint32_t t0, t1, t2, t3;
                ldsm4(t0, t1, t2, t3, B_H + off);
                bh[2 * nb][0] = t0; bh[2 * nb][1] = t1;
                bh[2 * nb + 1][0] = t2; bh[2 * nb + 1][1] = t3;
                ldsm4(t0, t1, t2, t3, B_L + off);
                bl[2 * nb][0] = t0; bl[2 * nb][1] = t1;
                bl[2 * nb + 1][0] = t2; bl[2 * nb + 1][1] = t3;
            }
#pragma unroll
            for (int mi = 0; mi < 2; mi++)
#pragma unroll
                for (int ni = 0; ni < 8; ni++) {
                    mma16816(d[mi][ni], ah[mi], bh[ni]);
                    mma16816(d[mi][ni], ah[mi], bl[ni]);
                    mma16816(d[mi][ni], al[mi], bh[ni]);
                }
        }
        __syncthreads();
    }

    /* ---- epilogue ---- */
    const int drow = lane >> 2;
    const int dcol = (lane & 3) * 2;
#pragma unroll
    for (int mi = 0; mi < 2; mi++) {
        const int m0 = blockM + wm * 32 + mi * 16 + drow;
#pragma unroll
        for (int ni = 0; ni < 8; ni++) {
            const int n = wn * 64 + ni * 8 + dcol;
            const float b0 = bias[n], b1 = bias[n + 1];
            *(float2*)(C + (long)m0 * HID + n) =
                make_float2(d[mi][ni][0] + b0, d[mi][ni][1] + b1);
            *(float2*)(C + (long)(m0 + 8) * HID + n) =
                make_float2(d[mi][ni][2] + b0, d[mi][ni][3] + b1);
        }
    }
}

/* ------------------------------------------------------------------ */
/* scan: h_t = tanh(xp_t + W_hh h_{t-1}); 128 CTAs x 2 batch          */
/* ------------------------------------------------------------------ */
__global__ __launch_bounds__(512)
void scan_kernel(const float* __restrict__ xp, const float* __restrict__ Whh,
                 float* __restrict__ hs)
{
    const int tid = threadIdx.x;
    const int j   = tid >> 2;
    const int seg = tid & 3;
    const int b0  = blockIdx.x * 2;

    __shared__ __align__(16) float hbuf[2][2][144];

    u64 w[16];
    const u64* wp = (const u64*)(Whh + j * HID + seg * 32);
#pragma unroll
    for (int i = 0; i < 16; i++) w[i] = wp[i];

    for (int i = tid; i < 2 * 144; i += 512) ((float*)hbuf[0])[i] = 0.f;

    const bool writer = (seg < 2);
    const int  wb     = seg;
    float xcur = 0.f;
    if (writer) xcur = xp[((long)0 * BATCH + b0 + wb) * HID + j];
    __syncthreads();

    int pp = 0;
    for (int t = 0; t < SEQ; ++t) {
        float xnext = 0.f;
        if (writer && t + 1 < SEQ)
            xnext = xp[((long)(t + 1) * BATCH + b0 + wb) * HID + j];

        u64 a0a = 0ull, a0b = 0ull, a1a = 0ull, a1b = 0ull;
        const ulonglong2* h0p = (const ulonglong2*)&hbuf[pp][0][seg * 36];
        const ulonglong2* h1p = (const ulonglong2*)&hbuf[pp][1][seg * 36];
#pragma unroll
        for (int i = 0; i < 8; i++) {
            const ulonglong2 h0v = h0p[i];
            fma2(a0a, w[2 * i + 0], h0v.x);
            fma2(a0b, w[2 * i + 1], h0v.y);
            const ulonglong2 h1v = h1p[i];
            fma2(a1a, w[2 * i + 0], h1v.x);
            fma2(a1b, w[2 * i + 1], h1v.y);
        }
        const float2 f0a = unpack2(a0a), f0b = unpack2(a0b);
        const float2 f1a = unpack2(a1a), f1b = unpack2(a1b);
        float s0 = (f0a.x + f0b.x) + (f0a.y + f0b.y);
        float s1 = (f1a.x + f1b.x) + (f1a.y + f1b.y);
        s0 += __shfl_xor_sync(0xffffffffu, s0, 1);
        s0 += __shfl_xor_sync(0xffffffffu, s0, 2);
        s1 += __shfl_xor_sync(0xffffffffu, s1, 1);
        s1 += __shfl_xor_sync(0xffffffffu, s1, 2);

        if (writer) {
            const float v = xcur + (wb == 0 ? s0 : s1);
            const float e = __expf(v + v);
            const float h = 1.f - __fdividef(2.f, e + 1.f);
            hbuf[pp ^ 1][wb][j + (j >> 5) * 4] = h;
            hs[((long)t * BATCH + b0 + wb) * HID + j] = h;
        }
        xcur = xnext;
        pp ^= 1;
        __syncthreads();
    }
}

/* ------------------------------------------------------------------ */
/* Fused MLP: L1 via warp-MMA (K=128, 2 chunks) -> smem y1 -> tail.   */
/* warps 4(m) x 2(n), warp tile 32x32.                                */
/* ------------------------------------------------------------------ */
#define MLP_A_H   0
#define MLP_A_L   16384
#define MLP_B_H   32768
#define MLP_B_L   40960
#define MLP_Y1    49152                         /* 128*66*4 = 33792 */
#define MLP_TW    (49152 + 33792)               /* tail weights     */
#define MLP_SMEM  (MLP_TW + (2048 + 512 + 128 + 8 + 32 + 16 + 8 + 4) * 4)

__global__ __launch_bounds__(256)
void mlp_kernel(const float* __restrict__ A,
                const __nv_bfloat16* __restrict__ W1h,
                const __nv_bfloat16* __restrict__ W1l,
                const float* __restrict__ b1,
                const float* __restrict__ W2, const float* __restrict__ b2,
                const float* __restrict__ W3, const float* __restrict__ b3,
                const float* __restrict__ W4, const float* __restrict__ b4,
                const float* __restrict__ W5, const float* __restrict__ b5,
                float* __restrict__ out)
{
    extern __shared__ __align__(1024) char sm[];
    const uint32_t base = smem_u32(sm);
    const uint32_t A_H = base + MLP_A_H, A_L = base + MLP_A_L;
    const uint32_t B_H = base + MLP_B_H, B_L = base + MLP_B_L;
    float* const y1s = (float*)(sm + MLP_Y1);    /* [128][66] */
    float* const sW2 = (float*)(sm + MLP_TW);    /* 2048 */
    float* const sW3 = sW2 + 2048;               /* 512  */
    float* const sW4 = sW3 + 512;                /* 128  */
    float* const sW5 = sW4 + 128;                /* 8    */
    float* const sb2 = sW5 + 8;                  /* 32   */
    float* const sb3 = sb2 + 32;                 /* 16   */
    float* const sb4 = sb3 + 16;                 /* 8    */
    float* const sb5 = sb4 + 8;                  /* 1    */

    const int tid  = threadIdx.x;
    const int lane = tid & 31;
    const int wid  = tid >> 5;
    const int wm   = wid & 3;
    const int wn   = wid >> 2;          /* 0..1, 32 cols each */
    const int blockM = blockIdx.x * 128;

    /* tail weights -> smem (independent of GEMM staging regions) */
    for (int i = tid; i < 2048; i += 256) sW2[i] = W2[i];
    for (int i = tid; i < 512;  i += 256) sW3[i] = W3[i];
    if (tid < 128) sW4[tid] = W4[tid];
    if (tid < 32)  sb2[tid] = b2[tid];
    if (tid < 16)  sb3[tid] = b3[tid];
    if (tid < 8) { sb4[tid] = b4[tid]; sW5[tid] = W5[tid]; }
    if (tid == 0)  sb5[0] = b5[0];

    float d[2][4][4];
#pragma unroll
    for (int mi = 0; mi < 2; mi++)
#pragma unroll
        for (int ni = 0; ni < 4; ni++)
#pragma unroll
            for (int q = 0; q < 4; q++) d[mi][ni][q] = 0.f;

    const int srow  = tid >> 1;
    const int shalf = (tid & 1) * 32;
    const float* Arow = A + (long)(blockM + srow) * HID;
    const uint32_t arow = srow * 128 + shalf * 2;

    /* B staging: 64 rows x 64 k per chunk; thread: n = tid&63, seg = tid>>6 */
    const int bn  = tid & 63;
    const int bsg = tid >> 6;            /* 0..3, 16 bf16 each */

    const int rowA = (lane & 7) + ((lane >> 3) & 1) * 8;
    const int kxA  = (lane >> 4) * 16;
    const int rowB = (lane & 7) + (lane >> 4) * 8;
    const int kxB  = ((lane >> 3) & 1) * 16;

    for (int c = 0; c < 2; ++c) {
#pragma unroll
        for (int i = 0; i < 8; i += 2) {
            uint32_t h0, h1, h2, h3, l0, l1, l2, l3;
            float4 v0 = *(const float4*)(Arow + c * 64 + shalf + i * 4);
            float4 v1 = *(const float4*)(Arow + c * 64 + shalf + (i + 1) * 4);
            split4(v0, h0, h1, l0, l1);
            split4(v1, h2, h3, l2, l3);
            const uint32_t off = SW128(arow + i * 8);
            STS128(A_H + off, h0, h1, h2, h3);
            STS128(A_L + off, l0, l1, l2, l3);
        }
        {
            const uint4 hv = *(const uint4*)(W1h + bn * HID + c * 64 + bsg * 16);
            const uint4 lv = *(const uint4*)(W1l + bn * HID + c * 64 + bsg * 16);
            const uint32_t off = SW128((uint32_t)(bn * 128 + bsg * 32));
            STS128(B_H + off, hv.x, hv.y, hv.z, hv.w);
            STS128(B_L + off, lv.x, lv.y, lv.z, lv.w);
            const uint4 hv2 = *(const uint4*)(W1h + bn * HID + c * 64 + bsg * 16 + 8);
            const uint4 lv2 = *(const uint4*)(W1l + bn * HID + c * 64 + bsg * 16 + 8);
            const uint32_t off2 = SW128((uint32_t)(bn * 128 + bsg * 32 + 16));
            STS128(B_H + off2, hv2.x, hv2.y, hv2.z, hv2.w);
            STS128(B_L + off2, lv2.x, lv2.y, lv2.z, lv2.w);
        }
        __syncthreads();

#pragma unroll
        for (int ks = 0; ks < 4; ++ks) {
            uint32_t ah[2][4], al[2][4];
#pragma unroll
            for (int mi = 0; mi < 2; mi++) {
                const uint32_t off = SW128((uint32_t)((wm * 32 + mi * 16 + rowA) * 128
                                                      + ks * 32 + kxA));
                ldsm4(ah[mi][0], ah[mi][1], ah[mi][2], ah[mi][3], A_H + off);
                ldsm4(al[mi][0], al[mi][1], al[mi][2], al[mi][3], A_L + off);
            }
            uint32_t bh[4][2], bl[4][2];
#pragma unroll
            for (int nb = 0; nb < 2; nb++) {
                const uint32_t off = SW128((uint32_t)((wn * 32 + nb * 16 + rowB) * 128
                                                      + ks * 32 + kxB));
                uint32_t t0, t1, t2, t3;
                ldsm4(t0, t1, t2, t3, B_H + off);
                bh[2 * nb][0] = t0; bh[2 * nb][1] = t1;
                bh[2 * nb + 1][0] = t2; bh[2 * nb + 1][1] = t3;
                ldsm4(t0, t1, t2, t3, B_L + off);
                bl[2 * nb][0] = t0; bl[2 * nb][1] = t1;
                bl[2 * nb + 1][0] = t2; bl[2 * nb + 1][1] = t3;
            }
#pragma unroll
            for (int mi = 0; mi < 2; mi++)
#pragma unroll
                for (int ni = 0; ni < 4; ni++) {
                    mma16816(d[mi][ni], ah[mi], bh[ni]);
                    mma16816(d[mi][ni], ah[mi], bl[ni]);
                    mma16816(d[mi][ni], al[mi], bh[ni]);
                }
        }
        __syncthreads();
    }

    /* L1 epilogue -> y1s (bias + leaky) */
    const int drow = lane >> 2;
    const int dcol = (lane & 3) * 2;
#pragma unroll
    for (int mi = 0; mi < 2; mi++) {
        const int m0 = wm * 32 + mi * 16 + drow;
#pragma unroll
        for (int ni = 0; ni < 4; ni++) {
            const int n = wn * 32 + ni * 8 + dcol;
            const float bb0 = b1[n], bb1 = b1[n + 1];
            float v0 = d[mi][ni][0] + bb0, v1 = d[mi][ni][1] + bb1;
            float v2 = d[mi][ni][2] + bb0, v3 = d[mi][ni][3] + bb1;
            v0 = v0 > 0.f ? v0 : ALPHA * v0;
            v1 = v1 > 0.f ? v1 : ALPHA * v1;
            v2 = v2 > 0.f ? v2 : ALPHA * v2;
            v3 = v3 > 0.f ? v3 : ALPHA * v3;
            *(float2*)&y1s[m0 * 66 + n]       = make_float2(v0, v1);
            *(float2*)&y1s[(m0 + 8) * 66 + n] = make_float2(v2, v3);
        }
    }
    __syncthreads();

    /* tail: 2 threads per row (k-split), shfl.xor(1) reductions */
    const int row  = tid >> 1;
    const int half = tid & 1;

    u64 ap[16];
    const u64* yr = (const u64*)&y1s[row * 66 + half * 32];
#pragma unroll
    for (int i = 0; i < 16; i++) ap[i] = yr[i];

    const u64* w2p = (const u64*)sW2;
    const u64* w3p = (const u64*)sW3;
    const u64* w4p = (const u64*)sW4;
    const u64* w5p = (const u64*)sW5;

    float y2[32];
#pragma unroll
    for (int o = 0; o < 32; o++) {
        u64 a = 0ull;
        const ulonglong2* wv = (const ulonglong2*)&w2p[o * 32 + half * 16];
#pragma unroll
        for (int k = 0; k < 8; k++) {
            const ulonglong2 wk = wv[k];
            fma2(a, ap[2 * k],     wk.x);
            fma2(a, ap[2 * k + 1], wk.y);
        }
        const float2 f = unpack2(a);
        float s = f.x + f.y;
        s += __shfl_xor_sync(0xffffffffu, s, 1);
        s += sb2[o];
        y2[o] = s > 0.f ? s : ALPHA * s;
    }

    u64 a2[8];
#pragma unroll
    for (int i = 0; i < 8; i++) a2[i] = pack2(y2[half * 16 + 2 * i], y2[half * 16 + 2 * i + 1]);
    float y3[16];
#pragma unroll
    for (int o = 0; o < 16; o++) {
        u64 a = 0ull;
        const ulonglong2* wv = (const ulonglong2*)&w3p[o * 16 + half * 8];
#pragma unroll
        for (int k = 0; k < 4; k++) {
            const ulonglong2 wk = wv[k];
            fma2(a, a2[2 * k],     wk.x);
            fma2(a, a2[2 * k + 1], wk.y);
        }
        const float2 f = unpack2(a);
        float s = f.x + f.y;
        s += __shfl_xor_sync(0xffffffffu, s, 1);
        s += sb3[o];
        y3[o] = s > 0.f ? s : ALPHA * s;
    }

    u64 a3[4];
#pragma unroll
    for (int i = 0; i < 4; i++) a3[i] = pack2(y3[half * 8 + 2 * i], y3[half * 8 + 2 * i + 1]);
    float y4[8];
#pragma unroll
    for (int o = 0; o < 8; o++) {
        u64 a = 0ull;
        const ulonglong2* wv = (const ulonglong2*)&w4p[o * 8 + half * 4];
#pragma unroll
        for (int k = 0; k < 2; k++) {
            const ulonglong2 wk = wv[k];
            fma2(a, a3[2 * k],     wk.x);
            fma2(a, a3[2 * k + 1], wk.y);
        }
        const float2 f = unpack2(a);
        float s = f.x + f.y;
        s += __shfl_xor_sync(0xffffffffu, s, 1);
        s += sb4[o];
        y4[o] = s > 0.f ? s : ALPHA * s;
    }

    u64 a4[2];
#pragma unroll
    for (int i = 0; i < 2; i++) a4[i] = pack2(y4[half * 4 + 2 * i], y4[half * 4 + 2 * i + 1]);
    {
        u64 a = 0ull;
        const ulonglong2 wk = *(const ulonglong2*)&w5p[half * 2];
        fma2(a, a4[0], wk.x);
        fma2(a, a4[1], wk.y);
        const float2 f = unpack2(a);
        float s = f.x + f.y;
        s += __shfl_xor_sync(0xffffffffu, s, 1);
        s += sb5[0];
        s = s > 0.f ? s : ALPHA * s;
        if (half == 0) out[blockM + row] = s;
    }
}

/* ------------------------------------------------------------------ */
extern "C" void kernel_launch(void* const* d_in, const int* in_sizes, int n_in,
                              void* d_out, int out_size)
{
    const float* x    = (const float*)d_in[0];
    const float* W_ih = (const float*)d_in[1];
    const float* W_hh = (const float*)d_in[2];
    const float* b_ih = (const float*)d_in[3];
    const float* b_hh = (const float*)d_in[4];
    const float* W1   = (const float*)d_in[5];
    const float* b1   = (const float*)d_in[6];
    const float* W2   = (const float*)d_in[7];
    const float* b2   = (const float*)d_in[8];
    const float* W3   = (const float*)d_in[9];
    const float* b3   = (const float*)d_in[10];
    const float* W4   = (const float*)d_in[11];
    const float* b4   = (const float*)d_in[12];
    const float* W5   = (const float*)d_in[13];
    const float* b5   = (const float*)d_in[14];
    float* out = (float*)d_out;

    float *xp, *hs, *bias;
    __nv_bfloat16 *Wbh, *Wbl, *W1h, *W1l;
    cudaGetSymbolAddress((void**)&xp,   g_xp);
    cudaGetSymbolAddress((void**)&hs,   g_hs);
    cudaGetSymbolAddress((void**)&Wbh,  g_Wbh);
    cudaGetSymbolAddress((void**)&Wbl,  g_Wbl);
    cudaGetSymbolAddress((void**)&W1h,  g_W1h);
    cudaGetSymbolAddress((void**)&W1l,  g_W1l);
    cudaGetSymbolAddress((void**)&bias, g_bias);

    /* idempotent, not a stream op — legal under graph capture; no static guard */
    cudaFuncSetAttribute(proj_mma_kernel,
                         cudaFuncAttributeMaxDynamicSharedMemorySize, PROJ_SMEM);
    cudaFuncSetAttribute(mlp_kernel,
                         cudaFuncAttributeMaxDynamicSharedMemorySize, MLP_SMEM);

    prep_kernel<<<(HID * KPAD + 255) / 256, 256>>>(W_ih, W1, b_ih, b_hh);
    proj_mma_kernel<<<MROWS / 128, 256, PROJ_SMEM>>>(x, Wbh, Wbl, bias, xp);
    scan_kernel<<<BATCH / 2, 512>>>(xp, W_hh, hs);
    mlp_kernel<<<MROWS / 128, 256, MLP_SMEM>>>(hs, W1h, W1l, b1,
                                               W2, b2, W3, b3, W4, b4, W5, b5, out);
}

// round 7
// speedup vs baseline: 1.3139x; 1.0767x over previous
#include <cuda_runtime.h>
#include <cuda_bf16.h>
#include <cstdint>

#define SEQ   512
#define BATCH 256
#define HID   128
#define MROWS (SEQ * BATCH)        /* 131072 */
#define KIN   300
#define KPAD  320                  /* 5 chunks of 64 */
#define ALPHA 0.1f

typedef unsigned long long u64;

/* ---------------- packed f32x2 helpers ----------------------------- */
__device__ __forceinline__ u64 pack2(float lo, float hi) {
    u64 r; asm("mov.b64 %0, {%1, %2};" : "=l"(r) : "f"(lo), "f"(hi)); return r;
}
__device__ __forceinline__ float2 unpack2(u64 v) {
    float2 f; asm("mov.b64 {%0, %1}, %2;" : "=f"(f.x), "=f"(f.y) : "l"(v)); return f;
}
__device__ __forceinline__ void fma2(u64 &acc, u64 a, u64 b) {
    asm("fma.rn.f32x2 %0, %1, %2, %0;" : "+l"(acc) : "l"(a), "l"(b));
}

/* ---------------- warp-MMA helpers (sm_80+ baseline PTX) ----------- */
__device__ __forceinline__ uint32_t smem_u32(const void* p) {
    uint32_t a;
    asm("{ .reg .u64 t; cvta.to.shared.u64 t, %1; cvt.u32.u64 %0, t; }" : "=r"(a) : "l"(p));
    return a;
}
#define SW128(off) ((off) ^ (((off) >> 3) & 0x70))

__device__ __forceinline__ void ldsm4(uint32_t &r0, uint32_t &r1, uint32_t &r2, uint32_t &r3,
                                      uint32_t addr) {
    asm volatile("ldmatrix.sync.aligned.m8n8.x4.shared.b16 {%0,%1,%2,%3}, [%4];"
                 : "=r"(r0), "=r"(r1), "=r"(r2), "=r"(r3) : "r"(addr));
}
__device__ __forceinline__ void mma16816(float* d, const uint32_t* a, const uint32_t* b) {
    asm volatile("mma.sync.aligned.m16n8k16.row.col.f32.bf16.bf16.f32 "
                 "{%0,%1,%2,%3}, {%4,%5,%6,%7}, {%8,%9}, {%0,%1,%2,%3};"
                 : "+f"(d[0]), "+f"(d[1]), "+f"(d[2]), "+f"(d[3])
                 : "r"(a[0]), "r"(a[1]), "r"(a[2]), "r"(a[3]), "r"(b[0]), "r"(b[1]));
}

/* cp.async 16B (LDGSTS) */
#define CP_A16(dst, src) \
    asm volatile("cp.async.ca.shared.global [%0], [%1], 16;" :: "r"(dst), "l"(src) : "memory")
#define CP_COMMIT() asm volatile("cp.async.commit_group;" ::: "memory")
#define CP_WAIT0()  asm volatile("cp.async.wait_group 0;" ::: "memory")

/* split one float4 into packed bf16x2 hi / lo words */
__device__ __forceinline__ void split4(float4 v, uint32_t &hp0, uint32_t &hp1,
                                       uint32_t &lp0, uint32_t &lp1) {
    const __nv_bfloat16 h0 = __float2bfloat16_rn(v.x);
    const __nv_bfloat16 h1 = __float2bfloat16_rn(v.y);
    const __nv_bfloat16 h2 = __float2bfloat16_rn(v.z);
    const __nv_bfloat16 h3 = __float2bfloat16_rn(v.w);
    __nv_bfloat162 t0 = __halves2bfloat162(h0, h1);
    __nv_bfloat162 t1 = __halves2bfloat162(h2, h3);
    hp0 = *(uint32_t*)&t0; hp1 = *(uint32_t*)&t1;
    __nv_bfloat162 u0 = __halves2bfloat162(__float2bfloat16_rn(v.x - __bfloat162float(h0)),
                                           __float2bfloat16_rn(v.y - __bfloat162float(h1)));
    __nv_bfloat162 u1 = __halves2bfloat162(__float2bfloat16_rn(v.z - __bfloat162float(h2)),
                                           __float2bfloat16_rn(v.w - __bfloat162float(h3)));
    lp0 = *(uint32_t*)&u0; lp1 = *(uint32_t*)&u1;
}

#define STS128(addr, a, b, c_, d_) \
    asm volatile("st.shared.v4.b32 [%0], {%1,%2,%3,%4};" :: "r"(addr), \
                 "r"(a), "r"(b), "r"(c_), "r"(d_) : "memory")

/* ---------------- scratch ------------------------------------------ */
__device__ float g_xp[MROWS * HID];
__device__ float g_hs[MROWS * HID];
__device__ __nv_bfloat16 g_Wbh[HID * KPAD];   /* W_ih hi  [n][k] */
__device__ __nv_bfloat16 g_Wbl[HID * KPAD];   /* W_ih lo  [n][k] */
__device__ __nv_bfloat16 g_W1h[64 * HID];     /* W1 hi    [n][k] */
__device__ __nv_bfloat16 g_W1l[64 * HID];     /* W1 lo    [n][k] */
__device__ float g_bias[HID];

/* ------------------------------------------------------------------ */
__global__ void prep_kernel(const float* __restrict__ W_ih,
                            const float* __restrict__ W1,
                            const float* __restrict__ b_ih,
                            const float* __restrict__ b_hh)
{
    const int i = blockIdx.x * 256 + threadIdx.x;
    if (i < HID * KPAD) {
        const int n = i / KPAD, k = i % KPAD;
        const float w = (k < KIN) ? W_ih[n * KIN + k] : 0.f;
        const __nv_bfloat16 h = __float2bfloat16_rn(w);
        g_Wbh[i] = h;
        g_Wbl[i] = __float2bfloat16_rn(w - __bfloat162float(h));
    }
    if (i < 64 * HID) {
        const float w = W1[i];
        const __nv_bfloat16 h = __float2bfloat16_rn(w);
        g_W1h[i] = h;
        g_W1l[i] = __float2bfloat16_rn(w - __bfloat162float(h));
    }
    if (i < HID) g_bias[i] = b_ih[i] + b_hh[i];
}

/* ------------------------------------------------------------------ */
/* proj: xp[M][128] = x[M][300] @ W_ih^T via warp-MMA bf16 3-product  */
/* CTA: 128x128, K in 5 chunks of 64; warps 4(m) x 2(n), tile 32x64.  */
/* B staged via cp.async; A converted fp32->bf16 hi/lo in registers.  */
/* ------------------------------------------------------------------ */
#define PROJ_SMEM (4 * 16384)

__global__ __launch_bounds__(256)
void proj_mma_kernel(const float* __restrict__ x,
                     const __nv_bfloat16* __restrict__ Wbh,
                     const __nv_bfloat16* __restrict__ Wbl,
                     const float* __restrict__ bias, float* __restrict__ C)
{
    extern __shared__ __align__(1024) char sm[];
    const uint32_t base = smem_u32(sm);
    const uint32_t A_H = base, A_L = base + 16384;
    const uint32_t B_H = base + 32768, B_L = base + 49152;

    const int tid  = threadIdx.x;
    const int lane = tid & 31;
    const int wid  = tid >> 5;
    const int wm   = wid & 3;          /* m tile 0..3 (32 rows) */
    const int wn   = wid >> 2;         /* n tile 0..1 (64 cols) */
    const int blockM = blockIdx.x * 128;

    float d[2][8][4];
#pragma unroll
    for (int mi = 0; mi < 2; mi++)
#pragma unroll
        for (int ni = 0; ni < 8; ni++)
#pragma unroll
            for (int q = 0; q < 4; q++) d[mi][ni][q] = 0.f;

    /* staging mapping: 2 threads per row, each does 32 k */
    const int srow  = tid >> 1;
    const int shalf = (tid & 1) * 32;
    const float* xrow = x + (long)(blockM + srow) * KIN;
    const uint32_t arow = srow * 128 + shalf * 2;

    /* ldmatrix lane->address components */
    const int rowA = (lane & 7) + ((lane >> 3) & 1) * 8;
    const int kxA  = (lane >> 4) * 16;                    /* bytes */
    const int rowB = (lane & 7) + (lane >> 4) * 8;
    const int kxB  = ((lane >> 3) & 1) * 16;

    for (int c = 0; c < 5; ++c) {
        /* ---- B via cp.async (overlaps A conversion below) ---- */
        {
            const __nv_bfloat16* bhp = Wbh + srow * KPAD + c * 64 + shalf;
            const __nv_bfloat16* blp = Wbl + srow * KPAD + c * 64 + shalf;
#pragma unroll
            for (int i = 0; i < 4; i++) {
                const uint32_t off = SW128(arow + i * 16);
                CP_A16(B_H + off, bhp + i * 8);
                CP_A16(B_L + off, blp + i * 8);
            }
            CP_COMMIT();
        }

        /* ---- stage A (fp32 -> bf16 hi/lo, swizzled) ---- */
#pragma unroll
        for (int i = 0; i < 8; i += 2) {
            uint32_t h0, h1, h2, h3, l0, l1, l2, l3;
            {
                const int gcol = c * 64 + shalf + i * 4;
                float4 v = make_float4(0.f, 0.f, 0.f, 0.f);
                if (gcol < KIN) v = *(const float4*)(xrow + gcol);
                split4(v, h0, h1, l0, l1);
            }
            {
                const int gcol = c * 64 + shalf + (i + 1) * 4;
                float4 v = make_float4(0.f, 0.f, 0.f, 0.f);
                if (gcol < KIN) v = *(const float4*)(xrow + gcol);
                split4(v, h2, h3, l2, l3);
            }
            const uint32_t off = SW128(arow + i * 8);
            STS128(A_H + off, h0, h1, h2, h3);
            STS128(A_L + off, l0, l1, l2, l3);
        }
        CP_WAIT0();
        __syncthreads();

        /* ---- compute: 4 k16 steps ---- */
#pragma unroll
        for (int ks = 0; ks < 4; ++ks) {
            uint32_t ah[2][4], al[2][4];
#pragma unroll
            for (int mi = 0; mi < 2; mi++) {
                const uint32_t off = SW128((uint32_t)((wm * 32 + mi * 16 + rowA) * 128
                                                      + ks * 32 + kxA));
                ldsm4(ah[mi][0], ah[mi][1], ah[mi][2], ah[mi][3], A_H + off);
                ldsm4(al[mi][0], al[mi][1], al[mi][2], al[mi][3], A_L + off);
            }
            uint32_t bh[8][2], bl[8][2];
#pragma unroll
            for (int nb = 0; nb < 4; nb++) {
                const uint32_t off = SW128((uint32_t)((wn * 64 + nb * 16 + rowB) * 128
                                                      + ks * 32 + kxB));
                uint32_t t0, t1, t2, t3;
                ldsm4(t0, t1, t2, t3, B_H + off);
                bh[2 * nb][0] = t0; bh[2 * nb][1] = t1;
                bh[2 * nb + 1][0] = t2; bh[2 * nb + 1][1] = t3;
                ldsm4(t0, t1, t2, t3, B_L + off);
                bl[2 * nb][0] = t0; bl[2 * nb][1] = t1;
                bl[2 * nb + 1][0] = t2; bl[2 * nb + 1][1] = t3;
            }
#pragma unroll
            for (int mi = 0; mi < 2; mi++)
#pragma unroll
                for (int ni = 0; ni < 8; ni++) {
                    mma16816(d[mi][ni], ah[mi], bh[ni]);
                    mma16816(d[mi][ni], ah[mi], bl[ni]);
                    mma16816(d[mi][ni], al[mi], bh[ni]);
                }
        }
        __syncthreads();
    }

    /* ---- epilogue ---- */
    const int drow = lane >> 2;
    const int dcol = (lane & 3) * 2;
#pragma unroll
    for (int mi = 0; mi < 2; mi++) {
        const int m0 = blockM + wm * 32 + mi * 16 + drow;
#pragma unroll
        for (int ni = 0; ni < 8; ni++) {
            const int n = wn * 64 + ni * 8 + dcol;
            const float b0 = bias[n], b1 = bias[n + 1];
            *(float2*)(C + (long)m0 * HID + n) =
                make_float2(d[mi][ni][0] + b0, d[mi][ni][1] + b1);
            *(float2*)(C + (long)(m0 + 8) * HID + n) =
                make_float2(d[mi][ni][2] + b0, d[mi][ni][3] + b1);
        }
    }
}

/* ------------------------------------------------------------------ */
/* scan v7: h_t = tanh(xp_t + W_hh h_{t-1}); 128 CTAs x 2 batch.      */
/* Register-blocked 2 outputs/thread: thread (jg, b, seg) holds two   */
/* W_hh row-slices in regs; h-slice read ONCE per thread per step     */
/* (halves smem read traffic vs 1-output/thread).                     */
/* tid = jg*8 + b*4 + seg.                                            */
/* ------------------------------------------------------------------ */
__global__ __launch_bounds__(512)
void scan_kernel(const float* __restrict__ xp, const float* __restrict__ Whh,
                 float* __restrict__ hs)
{
    const int tid = threadIdx.x;
    const int seg = tid & 3;
    const int b   = (tid >> 2) & 1;
    const int jg  = tid >> 3;          /* 0..63 */
    const int j0  = jg * 2;
    const int b0  = blockIdx.x * 2;

    __shared__ __align__(16) float hbuf[2][2][144];

    u64 w0[16], w1[16];
    const u64* wp0 = (const u64*)(Whh + j0 * HID + seg * 32);
    const u64* wp1 = (const u64*)(Whh + (j0 + 1) * HID + seg * 32);
#pragma unroll
    for (int i = 0; i < 16; i++) { w0[i] = wp0[i]; w1[i] = wp1[i]; }

    for (int i = tid; i < 2 * 2 * 144; i += 512) (&hbuf[0][0][0])[i] = 0.f;

    const bool writer = (seg == 0);
    float2 xcur = make_float2(0.f, 0.f);
    if (writer) xcur = *(const float2*)(xp + ((long)0 * BATCH + b0 + b) * HID + j0);
    __syncthreads();

    const int jpad = j0 + (j0 >> 5) * 4;
    int pp = 0;
    for (int t = 0; t < SEQ; ++t) {
        float2 xnext = make_float2(0.f, 0.f);
        if (writer && t + 1 < SEQ)
            xnext = *(const float2*)(xp + ((long)(t + 1) * BATCH + b0 + b) * HID + j0);

        u64 a0a = 0ull, a0b = 0ull, a1a = 0ull, a1b = 0ull;
        const ulonglong2* hp = (const ulonglong2*)&hbuf[pp][b][seg * 36];
#pragma unroll
        for (int i = 0; i < 8; i++) {
            const ulonglong2 hv = hp[i];
            fma2(a0a, w0[2 * i + 0], hv.x);
            fma2(a0b, w0[2 * i + 1], hv.y);
            fma2(a1a, w1[2 * i + 0], hv.x);
            fma2(a1b, w1[2 * i + 1], hv.y);
        }
        const float2 f0a = unpack2(a0a), f0b = unpack2(a0b);
        const float2 f1a = unpack2(a1a), f1b = unpack2(a1b);
        float s0 = (f0a.x + f0b.x) + (f0a.y + f0b.y);
        float s1 = (f1a.x + f1b.x) + (f1a.y + f1b.y);
        s0 += __shfl_xor_sync(0xffffffffu, s0, 1);
        s0 += __shfl_xor_sync(0xffffffffu, s0, 2);
        s1 += __shfl_xor_sync(0xffffffffu, s1, 1);
        s1 += __shfl_xor_sync(0xffffffffu, s1, 2);

        if (writer) {
            const float v0 = xcur.x + s0;
            const float v1 = xcur.y + s1;
            const float e0 = __expf(v0 + v0);
            const float e1 = __expf(v1 + v1);
            const float h0 = 1.f - __fdividef(2.f, e0 + 1.f);
            const float h1 = 1.f - __fdividef(2.f, e1 + 1.f);
            *(float2*)&hbuf[pp ^ 1][b][jpad] = make_float2(h0, h1);
            *(float2*)(hs + ((long)t * BATCH + b0 + b) * HID + j0) = make_float2(h0, h1);
        }
        xcur = xnext;
        pp ^= 1;
        __syncthreads();
    }
}

/* ------------------------------------------------------------------ */
/* Fused MLP: L1 via warp-MMA (K=128, 2 chunks) -> smem y1 -> tail.   */
/* warps 4(m) x 2(n), warp tile 32x32. B staged via cp.async.         */
/* ------------------------------------------------------------------ */
#define MLP_A_H   0
#define MLP_A_L   16384
#define MLP_B_H   32768
#define MLP_B_L   40960
#define MLP_Y1    49152                         /* 128*66*4 = 33792 */
#define MLP_TW    (49152 + 33792)               /* tail weights     */
#define MLP_SMEM  (MLP_TW + (2048 + 512 + 128 + 8 + 32 + 16 + 8 + 4) * 4)

__global__ __launch_bounds__(256)
void mlp_kernel(const float* __restrict__ A,
                const __nv_bfloat16* __restrict__ W1h,
                const __nv_bfloat16* __restrict__ W1l,
                const float* __restrict__ b1,
                const float* __restrict__ W2, const float* __restrict__ b2,
                const float* __restrict__ W3, const float* __restrict__ b3,
                const float* __restrict__ W4, const float* __restrict__ b4,
                const float* __restrict__ W5, const float* __restrict__ b5,
                float* __restrict__ out)
{
    extern __shared__ __align__(1024) char sm[];
    const uint32_t base = smem_u32(sm);
    const uint32_t A_H = base + MLP_A_H, A_L = base + MLP_A_L;
    const uint32_t B_H = base + MLP_B_H, B_L = base + MLP_B_L;
    float* const y1s = (float*)(sm + MLP_Y1);    /* [128][66] */
    float* const sW2 = (float*)(sm + MLP_TW);    /* 2048 */
    float* const sW3 = sW2 + 2048;               /* 512  */
    float* const sW4 = sW3 + 512;                /* 128  */
    float* const sW5 = sW4 + 128;                /* 8    */
    float* const sb2 = sW5 + 8;                  /* 32   */
    float* const sb3 = sb2 + 32;                 /* 16   */
    float* const sb4 = sb3 + 16;                 /* 8    */
    float* const sb5 = sb4 + 8;                  /* 1    */

    const int tid  = threadIdx.x;
    const int lane = tid & 31;
    const int wid  = tid >> 5;
    const int wm   = wid & 3;
    const int wn   = wid >> 2;          /* 0..1, 32 cols each */
    const int blockM = blockIdx.x * 128;

    /* tail weights -> smem (independent of GEMM staging regions) */
    for (int i = tid; i < 2048; i += 256) sW2[i] = W2[i];
    for (int i = tid; i < 512;  i += 256) sW3[i] = W3[i];
    if (tid < 128) sW4[tid] = W4[tid];
    if (tid < 32)  sb2[tid] = b2[tid];
    if (tid < 16)  sb3[tid] = b3[tid];
    if (tid < 8) { sb4[tid] = b4[tid]; sW5[tid] = W5[tid]; }
    if (tid == 0)  sb5[0] = b5[0];

    float d[2][4][4];
#pragma unroll
    for (int mi = 0; mi < 2; mi++)
#pragma unroll
        for (int ni = 0; ni < 4; ni++)
#pragma unroll
            for (int q = 0; q < 4; q++) d[mi][ni][q] = 0.f;

    const int srow  = tid >> 1;
    const int shalf = (tid & 1) * 32;
    const float* Arow = A + (long)(blockM + srow) * HID;
    const uint32_t arow = srow * 128 + shalf * 2;

    /* B staging via cp.async: bn = tid&63, bsg = tid>>6 (0..3) */
    const int bn  = tid & 63;
    const int bsg = tid >> 6;

    const int rowA = (lane & 7) + ((lane >> 3) & 1) * 8;
    const int kxA  = (lane >> 4) * 16;
    const int rowB = (lane & 7) + (lane >> 4) * 8;
    const int kxB  = ((lane >> 3) & 1) * 16;

    for (int c = 0; c < 2; ++c) {
        /* B via cp.async (overlaps A conversion) */
        {
            const __nv_bfloat16* bhp = W1h + bn * HID + c * 64 + bsg * 16;
            const __nv_bfloat16* blp = W1l + bn * HID + c * 64 + bsg * 16;
            const uint32_t o0 = SW128((uint32_t)(bn * 128 + bsg * 32));
            const uint32_t o1 = SW128((uint32_t)(bn * 128 + bsg * 32 + 16));
            CP_A16(B_H + o0, bhp);
            CP_A16(B_H + o1, bhp + 8);
            CP_A16(B_L + o0, blp);
            CP_A16(B_L + o1, blp + 8);
            CP_COMMIT();
        }
#pragma unroll
        for (int i = 0; i < 8; i += 2) {
            uint32_t h0, h1, h2, h3, l0, l1, l2, l3;
            float4 v0 = *(const float4*)(Arow + c * 64 + shalf + i * 4);
            float4 v1 = *(const float4*)(Arow + c * 64 + shalf + (i + 1) * 4);
            split4(v0, h0, h1, l0, l1);
            split4(v1, h2, h3, l2, l3);
            const uint32_t off = SW128(arow + i * 8);
            STS128(A_H + off, h0, h1, h2, h3);
            STS128(A_L + off, l0, l1, l2, l3);
        }
        CP_WAIT0();
        __syncthreads();

#pragma unroll
        for (int ks = 0; ks < 4; ++ks) {
            uint32_t ah[2][4], al[2][4];
#pragma unroll
            for (int mi = 0; mi < 2; mi++) {
                const uint32_t off = SW128((uint32_t)((wm * 32 + mi * 16 + rowA) * 128
                                                      + ks * 32 + kxA));
                ldsm4(ah[mi][0], ah[mi][1], ah[mi][2], ah[mi][3], A_H + off);
                ldsm4(al[mi][0], al[mi][1], al[mi][2], al[mi][3], A_L + off);
            }
            uint32_t bh[4][2], bl[4][2];
#pragma unroll
            for (int nb = 0; nb < 2; nb++) {
                const uint32_t off = SW128((uint32_t)((wn * 32 + nb * 16 + rowB) * 128
                                                      + ks * 32 + kxB));
                uint32_t t0, t1, t2, t3;
                ldsm4(t0, t1, t2, t3, B_H + off);
                bh[2 * nb][0] = t0; bh[2 * nb][1] = t1;
                bh[2 * nb + 1][0] = t2; bh[2 * nb + 1][1] = t3;
                ldsm4(t0, t1, t2, t3, B_L + off);
                bl[2 * nb][0] = t0; bl[2 * nb][1] = t1;
                bl[2 * nb + 1][0] = t2; bl[2 * nb + 1][1] = t3;
            }
#pragma unroll
            for (int mi = 0; mi < 2; mi++)
#pragma unroll
                for (int ni = 0; ni < 4; ni++) {
                    mma16816(d[mi][ni], ah[mi], bh[ni]);
                    mma16816(d[mi][ni], ah[mi], bl[ni]);
                    mma16816(d[mi][ni], al[mi], bh[ni]);
                }
        }
        __syncthreads();
    }

    /* L1 epilogue -> y1s (bias + leaky) */
    const int drow = lane >> 2;
    const int dcol = (lane & 3) * 2;
#pragma unroll
    for (int mi = 0; mi < 2; mi++) {
        const int m0 = wm * 32 + mi * 16 + drow;
#pragma unroll
        for (int ni = 0; ni < 4; ni++) {
            const int n = wn * 32 + ni * 8 + dcol;
            const float bb0 = b1[n], bb1 = b1[n + 1];
            float v0 = d[mi][ni][0] + bb0, v1 = d[mi][ni][1] + bb1;
            float v2 = d[mi][ni][2] + bb0, v3 = d[mi][ni][3] + bb1;
            v0 = v0 > 0.f ? v0 : ALPHA * v0;
            v1 = v1 > 0.f ? v1 : ALPHA * v1;
            v2 = v2 > 0.f ? v2 : ALPHA * v2;
            v3 = v3 > 0.f ? v3 : ALPHA * v3;
            *(float2*)&y1s[m0 * 66 + n]       = make_float2(v0, v1);
            *(float2*)&y1s[(m0 + 8) * 66 + n] = make_float2(v2, v3);
        }
    }
    __syncthreads();

    /* tail: 2 threads per row (k-split), shfl.xor(1) reductions */
    const int row  = tid >> 1;
    const int half = tid & 1;

    u64 ap[16];
    const u64* yr = (const u64*)&y1s[row * 66 + half * 32];
#pragma unroll
    for (int i = 0; i < 16; i++) ap[i] = yr[i];

    const u64* w2p = (const u64*)sW2;
    const u64* w3p = (const u64*)sW3;
    const u64* w4p = (const u64*)sW4;
    const u64* w5p = (const u64*)sW5;

    float y2[32];
#pragma unroll
    for (int o = 0; o < 32; o++) {
        u64 a = 0ull;
        const ulonglong2* wv = (const ulonglong2*)&w2p[o * 32 + half * 16];
#pragma unroll
        for (int k = 0; k < 8; k++) {
            const ulonglong2 wk = wv[k];
            fma2(a, ap[2 * k],     wk.x);
            fma2(a, ap[2 * k + 1], wk.y);
        }
        const float2 f = unpack2(a);
        float s = f.x + f.y;
        s += __shfl_xor_sync(0xffffffffu, s, 1);
        s += sb2[o];
        y2[o] = s > 0.f ? s : ALPHA * s;
    }

    u64 a2[8];
#pragma unroll
    for (int i = 0; i < 8; i++) a2[i] = pack2(y2[half * 16 + 2 * i], y2[half * 16 + 2 * i + 1]);
    float y3[16];
#pragma unroll
    for (int o = 0; o < 16; o++) {
        u64 a = 0ull;
        const ulonglong2* wv = (const ulonglong2*)&w3p[o * 16 + half * 8];
#pragma unroll
        for (int k = 0; k < 4; k++) {
            const ulonglong2 wk = wv[k];
            fma2(a, a2[2 * k],     wk.x);
            fma2(a, a2[2 * k + 1], wk.y);
        }
        const float2 f = unpack2(a);
        float s = f.x + f.y;
        s += __shfl_xor_sync(0xffffffffu, s, 1);
        s += sb3[o];
        y3[o] = s > 0.f ? s : ALPHA * s;
    }

    u64 a3[4];
#pragma unroll
    for (int i = 0; i < 4; i++) a3[i] = pack2(y3[half * 8 + 2 * i], y3[half * 8 + 2 * i + 1]);
    float y4[8];
#pragma unroll
    for (int o = 0; o < 8; o++) {
        u64 a = 0ull;
        const ulonglong2* wv = (const ulonglong2*)&w4p[o * 8 + half * 4];
#pragma unroll
        for (int k = 0; k < 2; k++) {
            const ulonglong2 wk = wv[k];
            fma2(a, a3[2 * k],     wk.x);
            fma2(a, a3[2 * k + 1], wk.y);
        }
        const float2 f = unpack2(a);
        float s = f.x + f.y;
        s += __shfl_xor_sync(0xffffffffu, s, 1);
        s += sb4[o];
        y4[o] = s > 0.f ? s : ALPHA * s;
    }

    u64 a4[2];
#pragma unroll
    for (int i = 0; i < 2; i++) a4[i] = pack2(y4[half * 4 + 2 * i], y4[half * 4 + 2 * i + 1]);
    {
        u64 a = 0ull;
        const ulonglong2 wk = *(const ulonglong2*)&w5p[half * 2];
        fma2(a, a4[0], wk.x);
        fma2(a, a4[1], wk.y);
        const float2 f = unpack2(a);
        float s = f.x + f.y;
        s += __shfl_xor_sync(0xffffffffu, s, 1);
        s += sb5[0];
        s = s > 0.f ? s : ALPHA * s;
        if (half == 0) out[blockM + row] = s;
    }
}

/* ------------------------------------------------------------------ */
extern "C" void kernel_launch(void* const* d_in, const int* in_sizes, int n_in,
                              void* d_out, int out_size)
{
    const float* x    = (const float*)d_in[0];
    const float* W_ih = (const float*)d_in[1];
    const float* W_hh = (const float*)d_in[2];
    const float* b_ih = (const float*)d_in[3];
    const float* b_hh = (const float*)d_in[4];
    const float* W1   = (const float*)d_in[5];
    const float* b1   = (const float*)d_in[6];
    const float* W2   = (const float*)d_in[7];
    const float* b2   = (const float*)d_in[8];
    const float* W3   = (const float*)d_in[9];
    const float* b3   = (const float*)d_in[10];
    const float* W4   = (const float*)d_in[11];
    const float* b4   = (const float*)d_in[12];
    const float* W5   = (const float*)d_in[13];
    const float* b5   = (const float*)d_in[14];
    float* out = (float*)d_out;

    float *xp, *hs, *bias;
    __nv_bfloat16 *Wbh, *Wbl, *W1h, *W1l;
    cudaGetSymbolAddress((void**)&xp,   g_xp);
    cudaGetSymbolAddress((void**)&hs,   g_hs);
    cudaGetSymbolAddress((void**)&Wbh,  g_Wbh);
    cudaGetSymbolAddress((void**)&Wbl,  g_Wbl);
    cudaGetSymbolAddress((void**)&W1h,  g_W1h);
    cudaGetSymbolAddress((void**)&W1l,  g_W1l);
    cudaGetSymbolAddress((void**)&bias, g_bias);

    cudaFuncSetAttribute(proj_mma_kernel,
                         cudaFuncAttributeMaxDynamicSharedMemorySize, PROJ_SMEM);
    cudaFuncSetAttribute(mlp_kernel,
                         cudaFuncAttributeMaxDynamicSharedMemorySize, MLP_SMEM);

    prep_kernel<<<(HID * KPAD + 255) / 256, 256>>>(W_ih, W1, b_ih, b_hh);
    proj_mma_kernel<<<MROWS / 128, 256, PROJ_SMEM>>>(x, Wbh, Wbl, bias, xp);
    scan_kernel<<<BATCH / 2, 512>>>(xp, W_hh, hs);
    mlp_kernel<<<MROWS / 128, 256, MLP_SMEM>>>(hs, W1h, W1l, b1,
                                               W2, b2, W3, b3, W4, b4, W5, b5, out);
}